// round 11
// baseline (speedup 1.0000x reference)
#include <cuda_runtime.h>
#include <cuda_bf16.h>

// Path signature, truncation level 4.
// path: (B=128, S=512, D=8) fp32 -> out: (B, 8+64+512+4096 = 4680) fp32
//
// One CTA per batch, 512 threads; thread m owns (i,j,k)=(m>>6,(m>>3)&7,m&7).
// Time is split into FOUR quarters. Stream A packs quarters (q0,q1) into the
// two lanes of f32x2 registers; stream B packs (q2,q3). Each thread runs the
// TWO INDEPENDENT packed recursions interleaved -> ILP 2 per warp, hiding the
// LDS/dependency stalls that capped fma-pipe utilization at ~53%.
// Combine: S = ((q0 (x) q1) (x) (q2 (x) q3)) via two smem Chen stages.

#define SD 512
#define DD 8
#define QT 128                 // steps per quarter
#define TRP_ROW 260            // padded floats per (stream,dim)-row
#define SIGF 4680              // floats per signature buffer
#define OUT_PER_B 4680

typedef unsigned long long u64;

__device__ __forceinline__ u64 dup2(float x) {
    u64 r; asm("mov.b64 %0, {%1, %1};" : "=l"(r) : "f"(x)); return r;
}
__device__ __forceinline__ u64 fmul2(u64 a, u64 b) {
    u64 r; asm("mul.rn.f32x2 %0, %1, %2;" : "=l"(r) : "l"(a), "l"(b)); return r;
}
__device__ __forceinline__ u64 fadd2(u64 a, u64 b) {
    u64 r; asm("add.rn.f32x2 %0, %1, %2;" : "=l"(r) : "l"(a), "l"(b)); return r;
}
__device__ __forceinline__ u64 ffma2(u64 a, u64 b, u64 c) {
    u64 r; asm("fma.rn.f32x2 %0, %1, %2, %3;" : "=l"(r) : "l"(a), "l"(b), "l"(c)); return r;
}
__device__ __forceinline__ void facc2(u64& d, u64 a, u64 b) {
    asm("fma.rn.f32x2 %0, %1, %2, %0;" : "+l"(d) : "l"(a), "l"(b));
}
__device__ __forceinline__ float lo2(u64 a) {
    float l, h; asm("mov.b64 {%0, %1}, %2;" : "=f"(l), "=f"(h) : "l"(a)); return l;
}
__device__ __forceinline__ float hi2(u64 a) {
    float l, h; asm("mov.b64 {%0, %1}, %2;" : "=f"(l), "=f"(h) : "l"(a)); return h;
}

// Store a signature (levels 1-4) into a 4680-float smem buffer.
__device__ __forceinline__ void store_sig(float* base, int m, int i, int k,
                                          float s1v, float s2v, float s3v,
                                          const float* s4v)
{
    *(float4*)(base + m * 8)     = make_float4(s4v[0], s4v[1], s4v[2], s4v[3]);
    *(float4*)(base + m * 8 + 4) = make_float4(s4v[4], s4v[5], s4v[6], s4v[7]);
    base[4096 + m] = s3v;
    if (k == 0)        base[4608 + (m >> 3)] = s2v;
    if ((m & 63) == 0) base[4672 + i]        = s1v;
}

// Truncated Chen product: OUT = L (x) R, R read from a 4680-float smem buffer.
__device__ __forceinline__ void chen(float l1, float l2, float l3, const float* l4,
                                     const float* base, int i, int j, int k, int m,
                                     float& o1, float& o2, float& o3, float* o4)
{
    const float* b4 = base;
    const float* b3 = base + 4096;
    const float* b2 = base + 4608;
    const float* b1 = base + 4672;

    float r1v[8];
    #pragma unroll
    for (int l = 0; l < 8; ++l) r1v[l] = b1[l];
    const float4 q0 = *(const float4*)(b2 + k * 8);
    const float4 q1 = *(const float4*)(b2 + k * 8 + 4);
    const float b2kl[8] = {q0.x,q0.y,q0.z,q0.w,q1.x,q1.y,q1.z,q1.w};
    const float b2jk = b2[j * 8 + k];
    const float4 r0 = *(const float4*)(b3 + j * 64 + k * 8);
    const float4 r1 = *(const float4*)(b3 + j * 64 + k * 8 + 4);
    const float b3jkl[8] = {r0.x,r0.y,r0.z,r0.w,r1.x,r1.y,r1.z,r1.w};
    const float4 w0 = *(const float4*)(b4 + m * 8);
    const float4 w1 = *(const float4*)(b4 + m * 8 + 4);
    const float b4m[8] = {w0.x,w0.y,w0.z,w0.w,w1.x,w1.y,w1.z,w1.w};
    const float b3m = b3[m];

    #pragma unroll
    for (int l = 0; l < 8; ++l) {
        float acc = l4[l] + b4m[l];
        acc = fmaf(l3, r1v[l],   acc);
        acc = fmaf(l2, b2kl[l],  acc);
        acc = fmaf(l1, b3jkl[l], acc);
        o4[l] = acc;
    }
    o3 = l3 + b3m;
    o3 = fmaf(l2, r1v[k], o3);
    o3 = fmaf(l1, b2jk,  o3);
    o2 = l2 + b2[m >> 3];
    o2 = fmaf(l1, r1v[j], o2);
    o1 = l1 + r1v[i];
}

__global__ __launch_bounds__(512, 1)
void signature_kernel(const float* __restrict__ path, float* __restrict__ out)
{
    // tables: [0..4096) rowp 2 streams x 128tp x 8 x float2   (16 KB)
    //         [4096..8256) trp 2 streams x 8 dims x 260       (16.6 KB)
    // combine reuses [0..9360): two 4680-float signature buffers
    __shared__ __align__(16) float sm[9360];

    const int b = blockIdx.x;
    const int m = threadIdx.x;            // 0..511
    const float* p = path + (size_t)b * SD * DD;

    // ---- Build pair-interleaved tables. Thread t computes inc[t].
    {
        const int t = m;
        float r[8];
        if (t < SD - 1) {
            const float4 a0 = *(const float4*)(p + t * DD);
            const float4 a1 = *(const float4*)(p + t * DD + 4);
            const float4 c0 = *(const float4*)(p + (t + 1) * DD);
            const float4 c1 = *(const float4*)(p + (t + 1) * DD + 4);
            r[0]=c0.x-a0.x; r[1]=c0.y-a0.y; r[2]=c0.z-a0.z; r[3]=c0.w-a0.w;
            r[4]=c1.x-a1.x; r[5]=c1.y-a1.y; r[6]=c1.z-a1.z; r[7]=c1.w-a1.w;
        } else {
            #pragma unroll
            for (int d = 0; d < 8; ++d) r[d] = 0.f;   // pad: exp(0)=identity
        }
        const int q  = t >> 7;            // quarter 0..3
        const int tp = t & (QT - 1);
        const int st = q >> 1;            // stream 0 (q0,q1) / 1 (q2,q3)
        const int sl = q & 1;             // lane: 0 = lo, 1 = hi
        #pragma unroll
        for (int l = 0; l < 8; ++l) sm[st * 2048 + tp * 16 + l * 2 + sl] = r[l];
        #pragma unroll
        for (int d = 0; d < 8; ++d)
            sm[4096 + (st * 8 + d) * TRP_ROW + tp * 2 + sl] = r[d];
    }
    __syncthreads();

    const int i = m >> 6;
    const int j = (m >> 3) & 7;
    const int k = m & 7;

    u64 sA1 = 0ull, sA2 = 0ull, sA3 = 0ull;
    u64 sB1 = 0ull, sB2 = 0ull, sB3 = 0ull;
    u64 sA4[8], sB4[8];
    #pragma unroll
    for (int l = 0; l < 8; ++l) { sA4[l] = 0ull; sB4[l] = 0ull; }

    const u64 C24 = dup2(1.f / 24.f);
    const u64 C6  = dup2(1.f / 6.f);
    const u64 CH  = dup2(0.5f);
    const u64 C3  = dup2(3.f);

    const float* __restrict__ row0 = sm;
    const float* __restrict__ row1 = sm + 2048;
    const float* __restrict__ pI0 = sm + 4096 + i * TRP_ROW;
    const float* __restrict__ pJ0 = sm + 4096 + j * TRP_ROW;
    const float* __restrict__ pK0 = sm + 4096 + k * TRP_ROW;
    const float* __restrict__ pI1 = sm + 4096 + (8 + i) * TRP_ROW;
    const float* __restrict__ pJ1 = sm + 4096 + (8 + j) * TRP_ROW;
    const float* __restrict__ pK1 = sm + 4096 + (8 + k) * TRP_ROW;

#define STEP(S1, S2, S3, S4, DI, DJ, DK, ROWB, TP_) do {                      \
    const ulonglong2 ra = *(const ulonglong2*)((ROWB) + (TP_) * 16);          \
    const ulonglong2 rb = *(const ulonglong2*)((ROWB) + (TP_) * 16 + 4);      \
    const ulonglong2 rc = *(const ulonglong2*)((ROWB) + (TP_) * 16 + 8);      \
    const ulonglong2 rd = *(const ulonglong2*)((ROWB) + (TP_) * 16 + 12);     \
    const u64 h  = fmul2((DJ), (DK));                                         \
    const u64 t1 = fmul2((DI), C24);                                          \
    const u64 t2 = ffma2(S1, C6, t1);                                         \
    const u64 c0 = ffma2(h, t2, S3);                                          \
    const u64 u  = fmul2(S2, (DK));                                           \
    const u64 c  = ffma2(u, CH, c0);                                          \
    const u64 g3 = ffma2(t2, C3, t1);   /* = s1/2 + dxi/6 */                  \
    S3 = ffma2(h, g3, fadd2(S3, u));                                          \
    S2 = ffma2((DJ), ffma2((DI), CH, S1), S2);                                \
    S1 = fadd2(S1, (DI));                                                     \
    facc2(S4[0], ra.x, c);                                                    \
    facc2(S4[1], ra.y, c);                                                    \
    facc2(S4[2], rb.x, c);                                                    \
    facc2(S4[3], rb.y, c);                                                    \
    facc2(S4[4], rc.x, c);                                                    \
    facc2(S4[5], rc.y, c);                                                    \
    facc2(S4[6], rd.x, c);                                                    \
    facc2(S4[7], rd.y, c);                                                    \
} while (0)

    #pragma unroll 1
    for (int g = 0; g < QT / 2; ++g) {
        // one LDS.128 per stream-axis serves two pair-steps
        const ulonglong2 diA = *(const ulonglong2*)(pI0 + g * 4);
        const ulonglong2 djA = *(const ulonglong2*)(pJ0 + g * 4);
        const ulonglong2 dkA = *(const ulonglong2*)(pK0 + g * 4);
        const ulonglong2 diB = *(const ulonglong2*)(pI1 + g * 4);
        const ulonglong2 djB = *(const ulonglong2*)(pJ1 + g * 4);
        const ulonglong2 dkB = *(const ulonglong2*)(pK1 + g * 4);
        // interleave independent streams A and B for ILP
        STEP(sA1, sA2, sA3, sA4, diA.x, djA.x, dkA.x, row0, 2 * g);
        STEP(sB1, sB2, sB3, sB4, diB.x, djB.x, dkB.x, row1, 2 * g);
        STEP(sA1, sA2, sA3, sA4, diA.y, djA.y, dkA.y, row0, 2 * g + 1);
        STEP(sB1, sB2, sB3, sB4, diB.y, djB.y, dkB.y, row1, 2 * g + 1);
    }
#undef STEP

    // ---- Unpack quarters: q0 = A.lo, q1 = A.hi, q2 = B.lo, q3 = B.hi.
    float q0_4[8], q1_4[8], q2_4[8], q3_4[8];
    #pragma unroll
    for (int l = 0; l < 8; ++l) {
        q0_4[l] = lo2(sA4[l]); q1_4[l] = hi2(sA4[l]);
        q2_4[l] = lo2(sB4[l]); q3_4[l] = hi2(sB4[l]);
    }
    const float q0_1 = lo2(sA1), q0_2 = lo2(sA2), q0_3 = lo2(sA3);
    const float q1_1 = hi2(sA1), q1_2 = hi2(sA2), q1_3 = hi2(sA3);
    const float q2_1 = lo2(sB1), q2_2 = lo2(sB2), q2_3 = lo2(sB3);
    const float q3_1 = hi2(sB1), q3_2 = hi2(sB2), q3_3 = hi2(sB3);

    // ---- Stage 1: write q1 -> buf0, q3 -> buf1; combine per stream.
    __syncthreads();                           // increment tables dead
    store_sig(sm,        m, i, k, q1_1, q1_2, q1_3, q1_4);
    store_sig(sm + SIGF, m, i, k, q3_1, q3_2, q3_3, q3_4);
    __syncthreads();

    float A1, A2, A3, A4[8];                   // S01 = q0 (x) q1
    chen(q0_1, q0_2, q0_3, q0_4, sm,        i, j, k, m, A1, A2, A3, A4);
    float B1, B2, B3, B4[8];                   // S23 = q2 (x) q3
    chen(q2_1, q2_2, q2_3, q2_4, sm + SIGF, i, j, k, m, B1, B2, B3, B4);

    // ---- Stage 2: S = S01 (x) S23.
    __syncthreads();                           // stage-1 reads done
    store_sig(sm, m, i, k, B1, B2, B3, B4);
    __syncthreads();

    float R1, R2, R3, R4[8];
    chen(A1, A2, A3, A4, sm, i, j, k, m, R1, R2, R3, R4);

    // ---- Emit: [s1(8) | s2(64) | s3(512) | s4(4096)] per batch.
    float* ob = out + (size_t)b * OUT_PER_B;
    float4* o4 = (float4*)(ob + 8 + 64 + 512 + m * 8);
    o4[0] = make_float4(R4[0], R4[1], R4[2], R4[3]);
    o4[1] = make_float4(R4[4], R4[5], R4[6], R4[7]);
    ob[8 + 64 + m] = R3;
    if (k == 0)        ob[8 + (m >> 3)] = R2;
    if ((m & 63) == 0) ob[m >> 6]       = R1;
}

extern "C" void kernel_launch(void* const* d_in, const int* in_sizes, int n_in,
                              void* d_out, int out_size)
{
    const float* path = (const float*)d_in[0];
    float* out = (float*)d_out;
    const int nb = in_sizes[0] / (SD * DD);   // 128
    signature_kernel<<<nb, 512>>>(path, out);
}

// round 12
// speedup vs baseline: 1.0411x; 1.0411x over previous
#include <cuda_runtime.h>
#include <cuda_bf16.h>

// Path signature, truncation level 4.
// path: (B=128, S=512, D=8) fp32 -> out: (B, 8+64+512+4096 = 4680) fp32
//
// One CTA per batch, 512 threads; thread m owns (i,j,k)=(m>>6,(m>>3)&7,m&7).
// Two time halves run in the two lanes of f32x2 registers: pair-interleaved
// smem tables deliver {halfA, halfB} operand pairs; packed coefficient
// {cA,cB} feeds fma.rn.f32x2 rank-1 updates directly.
//
// KEY CHANGE vs prior rounds: the per-dimension stream table is TIME-BLOCKED.
// Block g (128 bytes, 128B-aligned) holds all 8 dims' stream pairs for
// pair-times {2g, 2g+1}. A warp's dxi/dxj/dxk loads each touch exactly ONE
// 128B line (previously 1/4/8 lines), cutting L1tex wavefronts per STEP from
// ~10.5 to ~5.5 and removing the L1tex bottleneck that capped issue at ~50%.

#define SD 512
#define DD 8
#define HT 256                 // steps per half
#define OUT_PER_B (DD + DD*DD + DD*DD*DD + DD*DD*DD*DD)  // 4680
// stream table: 128 blocks x 32 floats (= 8 dims x {2 pair-times} x float2)
#define TRP2 4096              // float offset of stream table

typedef unsigned long long u64;

__device__ __forceinline__ u64 dup2(float x) {
    u64 r; asm("mov.b64 %0, {%1, %1};" : "=l"(r) : "f"(x)); return r;
}
__device__ __forceinline__ u64 fmul2(u64 a, u64 b) {
    u64 r; asm("mul.rn.f32x2 %0, %1, %2;" : "=l"(r) : "l"(a), "l"(b)); return r;
}
__device__ __forceinline__ u64 fadd2(u64 a, u64 b) {
    u64 r; asm("add.rn.f32x2 %0, %1, %2;" : "=l"(r) : "l"(a), "l"(b)); return r;
}
__device__ __forceinline__ u64 ffma2(u64 a, u64 b, u64 c) {
    u64 r; asm("fma.rn.f32x2 %0, %1, %2, %3;" : "=l"(r) : "l"(a), "l"(b), "l"(c)); return r;
}
__device__ __forceinline__ void facc2(u64& d, u64 a, u64 b) {
    asm("fma.rn.f32x2 %0, %1, %2, %0;" : "+l"(d) : "l"(a), "l"(b));
}
__device__ __forceinline__ float lo2(u64 a) {
    float l, h; asm("mov.b64 {%0, %1}, %2;" : "=f"(l), "=f"(h) : "l"(a)); return l;
}
__device__ __forceinline__ float hi2(u64 a) {
    float l, h; asm("mov.b64 {%0, %1}, %2;" : "=f"(l), "=f"(h) : "l"(a)); return h;
}

__global__ __launch_bounds__(512, 1)
void signature_kernel(const float* __restrict__ path, float* __restrict__ out)
{
    // [0 .. 4096)       rowp: 256 tp x 8 dims x float2 {halfA, halfB} (16 KB)
    // [4096 .. 8192)    trp2: 128 g-blocks x (8 dims x 2 tp x float2) (16 KB)
    // combine reuses [0 .. 4680)
    __shared__ __align__(16) float sm[8192];

    const int b = blockIdx.x;
    const int m = threadIdx.x;            // 0..511
    const float* p = path + (size_t)b * SD * DD;

    // ---- Build pair-interleaved tables. Thread t computes inc[t].
    {
        const int t = m;
        float r[8];
        if (t < SD - 1) {
            const float4 a0 = *(const float4*)(p + t * DD);
            const float4 a1 = *(const float4*)(p + t * DD + 4);
            const float4 c0 = *(const float4*)(p + (t + 1) * DD);
            const float4 c1 = *(const float4*)(p + (t + 1) * DD + 4);
            r[0]=c0.x-a0.x; r[1]=c0.y-a0.y; r[2]=c0.z-a0.z; r[3]=c0.w-a0.w;
            r[4]=c1.x-a1.x; r[5]=c1.y-a1.y; r[6]=c1.z-a1.z; r[7]=c1.w-a1.w;
        } else {
            #pragma unroll
            for (int d = 0; d < 8; ++d) r[d] = 0.f;   // pad: exp(0)=identity
        }
        const int tp = t & (HT - 1);      // pair-time
        const int sl = t >> 8;            // 0 = half A (lo), 1 = half B (hi)
        #pragma unroll
        for (int l = 0; l < 8; ++l) sm[tp * 16 + l * 2 + sl] = r[l];
        // time-blocked stream table: block g = tp>>1, slot pos = tp&1
        const int g  = tp >> 1;
        const int ps = tp & 1;
        #pragma unroll
        for (int d = 0; d < 8; ++d)
            sm[TRP2 + g * 32 + d * 4 + ps * 2 + sl] = r[d];
    }
    __syncthreads();

    const int i = m >> 6;
    const int j = (m >> 3) & 7;
    const int k = m & 7;

    u64 s1 = 0ull, s2 = 0ull, s3 = 0ull;
    u64 s4[8];
    #pragma unroll
    for (int l = 0; l < 8; ++l) s4[l] = 0ull;

    const u64 C24 = dup2(1.f / 24.f);
    const u64 C6  = dup2(1.f / 6.f);
    const u64 CH  = dup2(0.5f);
    const u64 C3  = dup2(3.f);

    const float* __restrict__ rowb = sm;
    const float* __restrict__ sI = sm + TRP2 + i * 4;   // + g*32 per iter
    const float* __restrict__ sJ = sm + TRP2 + j * 4;
    const float* __restrict__ sK = sm + TRP2 + k * 4;

#define STEP(DI, DJ, DK, TP_) do {                                           \
    const ulonglong2 ra = *(const ulonglong2*)(rowb + (TP_) * 16);            \
    const ulonglong2 rb = *(const ulonglong2*)(rowb + (TP_) * 16 + 4);        \
    const ulonglong2 rc = *(const ulonglong2*)(rowb + (TP_) * 16 + 8);        \
    const ulonglong2 rd = *(const ulonglong2*)(rowb + (TP_) * 16 + 12);       \
    const u64 h  = fmul2((DJ), (DK));                                         \
    const u64 t1 = fmul2((DI), C24);                                          \
    const u64 t2 = ffma2(s1, C6, t1);                                         \
    const u64 c0 = ffma2(h, t2, s3);                                          \
    const u64 u  = fmul2(s2, (DK));                                           \
    const u64 c  = ffma2(u, CH, c0);                                          \
    const u64 g3 = ffma2(t2, C3, t1);   /* = s1/2 + dxi/6 */                  \
    s3 = ffma2(h, g3, fadd2(s3, u));                                          \
    s2 = ffma2((DJ), ffma2((DI), CH, s1), s2);                                \
    s1 = fadd2(s1, (DI));                                                     \
    facc2(s4[0], ra.x, c);                                                    \
    facc2(s4[1], ra.y, c);                                                    \
    facc2(s4[2], rb.x, c);                                                    \
    facc2(s4[3], rb.y, c);                                                    \
    facc2(s4[4], rc.x, c);                                                    \
    facc2(s4[5], rc.y, c);                                                    \
    facc2(s4[6], rd.x, c);                                                    \
    facc2(s4[7], rd.y, c);                                                    \
} while (0)

    #pragma unroll 4
    for (int g = 0; g < HT / 2; ++g) {
        // each stream load: one LDS.128, ONE 128B line per warp
        const ulonglong2 di = *(const ulonglong2*)(sI + g * 32);
        const ulonglong2 dj = *(const ulonglong2*)(sJ + g * 32);
        const ulonglong2 dk = *(const ulonglong2*)(sK + g * 32);
        STEP(di.x, dj.x, dk.x, 2 * g);
        STEP(di.y, dj.y, dk.y, 2 * g + 1);
    }
#undef STEP

    // ---- Split packed state: A = lo lanes (first half), B = hi lanes.
    float a4[8], b4v[8];
    #pragma unroll
    for (int l = 0; l < 8; ++l) { a4[l] = lo2(s4[l]); b4v[l] = hi2(s4[l]); }
    const float a1 = lo2(s1), a2 = lo2(s2), a3 = lo2(s3);
    const float bb1s = hi2(s1), bb2s = hi2(s2), bb3s = hi2(s3);

    // ---- Chen combine: S = A (x) B through shared memory (aliases tables).
    float* b4 = sm;            // 4096 floats
    float* b3 = sm + 4096;     // 512
    float* b2 = sm + 4608;     // 64
    float* b1 = sm + 4672;     // 8

    __syncthreads();           // done reading increment tables

    *(float4*)(b4 + m * 8)     = make_float4(b4v[0], b4v[1], b4v[2], b4v[3]);
    *(float4*)(b4 + m * 8 + 4) = make_float4(b4v[4], b4v[5], b4v[6], b4v[7]);
    b3[m] = bb3s;
    if (k == 0)        b2[m >> 3] = bb2s;
    if ((m & 63) == 0) b1[i]      = bb1s;
    __syncthreads();

    float bb1[8];
    #pragma unroll
    for (int l = 0; l < 8; ++l) bb1[l] = b1[l];
    const float4 q0 = *(const float4*)(b2 + k * 8);
    const float4 q1 = *(const float4*)(b2 + k * 8 + 4);
    const float b2kl[8] = {q0.x,q0.y,q0.z,q0.w,q1.x,q1.y,q1.z,q1.w};
    const float b2jk = b2[j * 8 + k];
    const float4 r0 = *(const float4*)(b3 + j * 64 + k * 8);
    const float4 r1 = *(const float4*)(b3 + j * 64 + k * 8 + 4);
    const float b3jkl[8] = {r0.x,r0.y,r0.z,r0.w,r1.x,r1.y,r1.z,r1.w};
    const float4 w0 = *(const float4*)(b4 + m * 8);
    const float4 w1 = *(const float4*)(b4 + m * 8 + 4);
    const float b4m[8] = {w0.x,w0.y,w0.z,w0.w,w1.x,w1.y,w1.z,w1.w};
    const float bb3m = b3[m];

    float r4[8];
    #pragma unroll
    for (int l = 0; l < 8; ++l) {
        float acc = a4[l] + b4m[l];
        acc = fmaf(a3, bb1[l],   acc);
        acc = fmaf(a2, b2kl[l],  acc);
        acc = fmaf(a1, b3jkl[l], acc);
        r4[l] = acc;
    }
    float r3 = a3 + bb3m;
    r3 = fmaf(a2, bb1[k], r3);
    r3 = fmaf(a1, b2jk,  r3);
    float r2 = a2 + b2[m >> 3];
    r2 = fmaf(a1, bb1[j], r2);
    const float r1s = a1 + bb1[i];

    // ---- Emit: [s1(8) | s2(64) | s3(512) | s4(4096)] per batch.
    float* ob = out + (size_t)b * OUT_PER_B;
    float4* o4 = (float4*)(ob + DD + DD*DD + DD*DD*DD + m * 8);
    o4[0] = make_float4(r4[0], r4[1], r4[2], r4[3]);
    o4[1] = make_float4(r4[4], r4[5], r4[6], r4[7]);
    ob[DD + DD*DD + m] = r3;
    if (k == 0)        ob[DD + (m >> 3)] = r2;
    if ((m & 63) == 0) ob[m >> 6]        = r1s;
}

extern "C" void kernel_launch(void* const* d_in, const int* in_sizes, int n_in,
                              void* d_out, int out_size)
{
    const float* path = (const float*)d_in[0];
    float* out = (float*)d_out;
    const int nb = in_sizes[0] / (SD * DD);   // 128
    signature_kernel<<<nb, 512>>>(path, out);
}